// round 2
// baseline (speedup 1.0000x reference)
#include <cuda_runtime.h>
#include <cstdint>

#define Nn 100000
#define Ee 800000

// ---------------- scratch (static __device__ globals; no runtime alloc) ----------------
__device__ int   g_is64;
__device__ int   g_degi[Nn];
__device__ float g_dinv[Nn];
__device__ float g_cinv[Nn];
__device__ int   g_rowptr[Nn + 1];
__device__ int   g_fill[Nn];
__device__ int   g_colidx[Ee];
__device__ float g_hA[(size_t)Nn * 256];
__device__ float g_hB[(size_t)Nn * 256];
__device__ float g_agg[(size_t)Nn * 256];

// ---------------- dtype detection: int32 vs int64 edge_index ----------------
// If int64 (LE), high 32-bit word of each value is 0 (indices in [0, 2^31)).
// If int32, odd words are random node indices -> essentially never all zero.
__global__ void k_detect(const int* __restrict__ w) {
    if (threadIdx.x == 0 && blockIdx.x == 0) {
        int is64 = 1;
        for (int i = 0; i < 256; i++)
            if (w[2 * i + 1] != 0) { is64 = 0; break; }
        g_is64 = is64;
    }
}

__device__ __forceinline__ int edge_at(const void* ei, int half, int e) {
    if (g_is64) return (int)((const long long*)ei)[(size_t)half * Ee + e];
    return ((const int*)ei)[(size_t)half * Ee + e];
}

// ---------------- small kernels ----------------
__global__ void k_zero(int* p, int n) {
    int i = blockIdx.x * blockDim.x + threadIdx.x;
    if (i < n) p[i] = 0;
}

__global__ void k_count(const void* __restrict__ ei, int* __restrict__ degi) {
    int e = blockIdx.x * blockDim.x + threadIdx.x;
    if (e < Ee) {
        int r = edge_at(ei, 0, e);
        atomicAdd(&degi[r], 1);
    }
}

__global__ void k_stats(const int* __restrict__ degi, float* __restrict__ dinv,
                        float* __restrict__ cinv) {
    int i = blockIdx.x * blockDim.x + threadIdx.x;
    if (i < Nn) {
        int d = degi[i];
        dinv[i] = (d > 0) ? rsqrtf((float)d) : 0.0f;
        cinv[i] = 1.0f / (float)max(d, 1);
    }
}

// one-block exclusive scan of degi -> rowptr (and copy to fill cursors)
__global__ void k_scan(const int* __restrict__ cnt, int* __restrict__ rowptr,
                       int* __restrict__ fill) {
    __shared__ int wsum[32];
    __shared__ int carry;
    int tid = threadIdx.x, lane = tid & 31, wid = tid >> 5;
    if (tid == 0) carry = 0;
    __syncthreads();
    for (int base = 0; base < Nn; base += 1024) {
        int i = base + tid;
        int v = (i < Nn) ? cnt[i] : 0;
        int inc = v;
        #pragma unroll
        for (int o = 1; o < 32; o <<= 1) {
            int t = __shfl_up_sync(0xFFFFFFFFu, inc, o);
            if (lane >= o) inc += t;
        }
        if (lane == 31) wsum[wid] = inc;
        __syncthreads();
        if (wid == 0) {
            int s = wsum[lane];
            #pragma unroll
            for (int o = 1; o < 32; o <<= 1) {
                int t = __shfl_up_sync(0xFFFFFFFFu, s, o);
                if (lane >= o) s += t;
            }
            wsum[lane] = s;
        }
        __syncthreads();
        int woff  = wid ? wsum[wid - 1] : 0;
        int total = wsum[31];
        int ex = carry + woff + inc - v;
        if (i < Nn) { rowptr[i] = ex; fill[i] = ex; }
        __syncthreads();
        if (tid == 0) carry += total;
        __syncthreads();
    }
    if (threadIdx.x == 0) rowptr[Nn] = carry;
}

__global__ void k_fill(const void* __restrict__ ei, int* __restrict__ fill,
                       int* __restrict__ colidx) {
    int e = blockIdx.x * blockDim.x + threadIdx.x;
    if (e < Ee) {
        int r = edge_at(ei, 0, e);
        int c = edge_at(ei, 1, e);
        int p = atomicAdd(&fill[r], 1);
        colidx[p] = c;
    }
}

// ---------------- aggregation (CSR gather-sum) ----------------
// GCN: out[i] = dinv[i] * sum_e h[col]*dinv[col];  MEAN: out[i] = cinv[i] * sum_e h[col]
template <int C, bool GCN>
__global__ void k_agg(const float* __restrict__ h, float* __restrict__ out,
                      const int* __restrict__ rowptr, const int* __restrict__ colidx,
                      const float* __restrict__ dinv, const float* __restrict__ cinv) {
    constexpr int TPN = C / 4;        // threads per node (float4 lanes)
    constexpr int NPB = 256 / TPN;    // nodes per block
    int node = blockIdx.x * NPB + threadIdx.x / TPN;
    if (node >= Nn) return;
    int lane = threadIdx.x % TPN;
    int s = rowptr[node], e = rowptr[node + 1];
    const float4* h4 = (const float4*)h;
    float4 acc = make_float4(0.f, 0.f, 0.f, 0.f);
    for (int p = s; p < e; p++) {
        int j = colidx[p];
        float w = GCN ? dinv[j] : 1.0f;
        float4 v = __ldg(&h4[(size_t)j * TPN + lane]);
        acc.x += v.x * w; acc.y += v.y * w; acc.z += v.z * w; acc.w += v.w * w;
    }
    float sc = GCN ? dinv[node] : cinv[node];
    acc.x *= sc; acc.y *= sc; acc.z *= sc; acc.w *= sc;
    ((float4*)out)[(size_t)node * TPN + lane] = acc;
}

// ---------------- fused dual GEMM: out = f(A0@B0 [+ A1@B1] + bias) ----------------
// epilogue: if res: out = res + alpha*(acc+bias); else (+relu optional)
#define BM 64
#define BN 64
#define BK 16
__global__ void __launch_bounds__(256)
k_gemm(const float* __restrict__ A0, const float* __restrict__ B0,
       const float* __restrict__ A1, const float* __restrict__ B1,
       const float* __restrict__ bias,
       const float* __restrict__ res, const float* __restrict__ alphaPtr, int alphaIdx,
       float* __restrict__ out, int n, int K, int Cout, int doRelu) {
    __shared__ float sA[BK][BM + 4];
    __shared__ float sB[BK][BN];
    int bm = blockIdx.y * BM;
    int bn = blockIdx.x * BN;
    int tx = threadIdx.x % 16;   // n
    int ty = threadIdx.x / 16;   // m
    float4 acc[4];
    #pragma unroll
    for (int u = 0; u < 4; u++) acc[u] = make_float4(0.f, 0.f, 0.f, 0.f);

    #pragma unroll 1
    for (int pass = 0; pass < 2; pass++) {
        const float* A = pass ? A1 : A0;
        const float* B = pass ? B1 : B0;
        if (!A) continue;
        for (int k0 = 0; k0 < K; k0 += BK) {
            // A tile: 64 rows x 16 k; kk fastest in thread id -> coalesced 64B rows
            #pragma unroll
            for (int t = threadIdx.x; t < BM * BK; t += 256) {
                int m = t / BK, kk = t % BK;
                int gr = bm + m;
                sA[kk][m] = (gr < n) ? A[(size_t)gr * K + k0 + kk] : 0.f;
            }
            // B tile: 16 k x 64 cols; nn fastest -> coalesced
            #pragma unroll
            for (int t = threadIdx.x; t < BK * BN; t += 256) {
                int nn = t % BN, kk = t / BN;
                int gc = bn + nn;
                sB[kk][nn] = (gc < Cout) ? B[(size_t)(k0 + kk) * Cout + gc] : 0.f;
            }
            __syncthreads();
            #pragma unroll
            for (int kk = 0; kk < BK; kk++) {
                float4 bv = *(const float4*)&sB[kk][tx * 4];
                float a0 = sA[kk][ty * 4 + 0];
                float a1 = sA[kk][ty * 4 + 1];
                float a2 = sA[kk][ty * 4 + 2];
                float a3 = sA[kk][ty * 4 + 3];
                acc[0].x += a0 * bv.x; acc[0].y += a0 * bv.y; acc[0].z += a0 * bv.z; acc[0].w += a0 * bv.w;
                acc[1].x += a1 * bv.x; acc[1].y += a1 * bv.y; acc[1].z += a1 * bv.z; acc[1].w += a1 * bv.w;
                acc[2].x += a2 * bv.x; acc[2].y += a2 * bv.y; acc[2].z += a2 * bv.z; acc[2].w += a2 * bv.w;
                acc[3].x += a3 * bv.x; acc[3].y += a3 * bv.y; acc[3].z += a3 * bv.z; acc[3].w += a3 * bv.w;
            }
            __syncthreads();
        }
    }

    float alpha = alphaPtr ? __ldg(&alphaPtr[alphaIdx]) : 0.f;
    #pragma unroll
    for (int u = 0; u < 4; u++) {
        int gr = bm + ty * 4 + u;
        if (gr >= n) continue;
        float av[4] = {acc[u].x, acc[u].y, acc[u].z, acc[u].w};
        #pragma unroll
        for (int v = 0; v < 4; v++) {
            int gc = bn + tx * 4 + v;
            if (gc >= Cout) continue;
            float val = av[v] + __ldg(&bias[gc]);
            if (doRelu) val = fmaxf(val, 0.f);
            if (res) val = res[(size_t)gr * Cout + gc] + alpha * val;
            out[(size_t)gr * Cout + gc] = val;
        }
    }
}

// ---------------- launch ----------------
extern "C" void kernel_launch(void* const* d_in, const int* in_sizes, int n_in,
                              void* d_out, int out_size) {
    const float* x     = (const float*)d_in[0];
    const void*  ei    = d_in[1];
    const float* alpha = (const float*)d_in[2];
    const float* W0 = (const float*)d_in[3];  const float* b0 = (const float*)d_in[4];
    const float* W1 = (const float*)d_in[5];  const float* R1 = (const float*)d_in[6];  const float* b1 = (const float*)d_in[7];
    const float* W2 = (const float*)d_in[8];  const float* R2 = (const float*)d_in[9];  const float* b2 = (const float*)d_in[10];
    const float* W3 = (const float*)d_in[11]; const float* b3 = (const float*)d_in[12];
    const float* W4 = (const float*)d_in[13]; const float* R4 = (const float*)d_in[14]; const float* b4 = (const float*)d_in[15];
    float* out = (float*)d_out;

    float *hA, *hB, *agg, *dinv, *cinv;
    int *degi, *rowptr, *fill, *colidx;
    cudaGetSymbolAddress((void**)&degi,   g_degi);
    cudaGetSymbolAddress((void**)&dinv,   g_dinv);
    cudaGetSymbolAddress((void**)&cinv,   g_cinv);
    cudaGetSymbolAddress((void**)&rowptr, g_rowptr);
    cudaGetSymbolAddress((void**)&fill,   g_fill);
    cudaGetSymbolAddress((void**)&colidx, g_colidx);
    cudaGetSymbolAddress((void**)&hA,     g_hA);
    cudaGetSymbolAddress((void**)&hB,     g_hB);
    cudaGetSymbolAddress((void**)&agg,    g_agg);

    const int NB_N = (Nn + 255) / 256;
    const int NB_E = (Ee + 255) / 256;
    const int MT   = (Nn + BM - 1) / BM;   // 1563

    // graph structure (rebuilt every call; deterministic work)
    k_detect<<<1, 32>>>((const int*)ei);
    k_zero<<<NB_N, 256>>>(degi, Nn);
    k_count<<<NB_E, 256>>>(ei, degi);
    k_stats<<<NB_N, 256>>>(degi, dinv, cinv);
    k_scan<<<1, 1024>>>(degi, rowptr, fill);
    k_fill<<<NB_E, 256>>>(ei, fill, colidx);

    // layer 0: GCN, C=128, rezero residual (alpha[0])
    k_agg<128, true><<<Nn / 8, 256>>>(x, agg, rowptr, colidx, dinv, cinv);
    k_gemm<<<dim3(2, MT), 256>>>(agg, W0, nullptr, nullptr, b0, x, alpha, 0, hA, Nn, 128, 128, 0);

    // layer 1: SAGE 128->256 + relu
    k_agg<128, false><<<Nn / 8, 256>>>(hA, agg, rowptr, colidx, dinv, cinv);
    k_gemm<<<dim3(4, MT), 256>>>(agg, W1, hA, R1, b1, nullptr, nullptr, 0, hB, Nn, 128, 256, 1);

    // layer 2: SAGE 256->256 + relu
    k_agg<256, false><<<Nn / 4, 256>>>(hB, agg, rowptr, colidx, dinv, cinv);
    k_gemm<<<dim3(4, MT), 256>>>(agg, W2, hB, R2, b2, nullptr, nullptr, 0, hA, Nn, 256, 256, 1);

    // layer 3: GCN, C=256, rezero residual (alpha[3])
    k_agg<256, true><<<Nn / 4, 256>>>(hA, agg, rowptr, colidx, dinv, cinv);
    k_gemm<<<dim3(4, MT), 256>>>(agg, W3, nullptr, nullptr, b3, hA, alpha, 3, hB, Nn, 256, 256, 0);

    // layer 4: SAGE 256->112, no relu
    k_agg<256, false><<<Nn / 4, 256>>>(hB, agg, rowptr, colidx, dinv, cinv);
    k_gemm<<<dim3(2, MT), 256>>>(agg, W4, hB, R4, b4, nullptr, nullptr, 0, out, Nn, 256, 112, 0);
}

// round 3
// speedup vs baseline: 1.2635x; 1.2635x over previous
#include <cuda_runtime.h>
#include <cstdint>

#define Nn 100000
#define Ee 800000
typedef unsigned long long ull;

// ---------------- scratch (static __device__ globals; no runtime alloc) ----------------
__device__ int   g_is64;
__device__ int   g_degi[Nn];
__device__ float g_dinv[Nn];
__device__ float g_cinv[Nn];
__device__ int   g_rowptr[Nn + 1];
__device__ int   g_fill[Nn];
__device__ int   g_colidx[Ee];
__device__ float g_hA[(size_t)Nn * 256];
__device__ float g_hB[(size_t)Nn * 256];
__device__ float g_agg[(size_t)Nn * 256];

// ---------------- packed f32x2 helpers ----------------
__device__ __forceinline__ ull pack2(float x, float y) {
    ull r;
    asm("mov.b64 %0, {%1, %2};" : "=l"(r) : "f"(x), "f"(y));
    return r;
}
__device__ __forceinline__ void unpack2(ull v, float& x, float& y) {
    asm("mov.b64 {%0, %1}, %2;" : "=f"(x), "=f"(y) : "l"(v));
}
__device__ __forceinline__ ull ffma2(ull a, ull b, ull c) {
    ull d;
    asm("fma.rn.f32x2 %0, %1, %2, %3;" : "=l"(d) : "l"(a), "l"(b), "l"(c));
    return d;
}

// ---------------- dtype detection: int32 vs int64 edge_index ----------------
__global__ void k_detect(const int* __restrict__ w) {
    if (threadIdx.x == 0 && blockIdx.x == 0) {
        int is64 = 1;
        for (int i = 0; i < 256; i++)
            if (w[2 * i + 1] != 0) { is64 = 0; break; }
        g_is64 = is64;
    }
}

__device__ __forceinline__ int edge_at(const void* ei, int half, int e) {
    if (g_is64) return (int)((const long long*)ei)[(size_t)half * Ee + e];
    return ((const int*)ei)[(size_t)half * Ee + e];
}

// ---------------- small kernels ----------------
__global__ void k_zero(int* p, int n) {
    int i = blockIdx.x * blockDim.x + threadIdx.x;
    if (i < n) p[i] = 0;
}

__global__ void k_count(const void* __restrict__ ei, int* __restrict__ degi) {
    int e = blockIdx.x * blockDim.x + threadIdx.x;
    if (e < Ee) atomicAdd(&degi[edge_at(ei, 0, e)], 1);
}

__global__ void k_stats(const int* __restrict__ degi, float* __restrict__ dinv,
                        float* __restrict__ cinv) {
    int i = blockIdx.x * blockDim.x + threadIdx.x;
    if (i < Nn) {
        int d = degi[i];
        dinv[i] = (d > 0) ? rsqrtf((float)d) : 0.0f;
        cinv[i] = 1.0f / (float)max(d, 1);
    }
}

__global__ void k_scan(const int* __restrict__ cnt, int* __restrict__ rowptr,
                       int* __restrict__ fill) {
    __shared__ int wsum[32];
    __shared__ int carry;
    int tid = threadIdx.x, lane = tid & 31, wid = tid >> 5;
    if (tid == 0) carry = 0;
    __syncthreads();
    for (int base = 0; base < Nn; base += 1024) {
        int i = base + tid;
        int v = (i < Nn) ? cnt[i] : 0;
        int inc = v;
        #pragma unroll
        for (int o = 1; o < 32; o <<= 1) {
            int t = __shfl_up_sync(0xFFFFFFFFu, inc, o);
            if (lane >= o) inc += t;
        }
        if (lane == 31) wsum[wid] = inc;
        __syncthreads();
        if (wid == 0) {
            int s = wsum[lane];
            #pragma unroll
            for (int o = 1; o < 32; o <<= 1) {
                int t = __shfl_up_sync(0xFFFFFFFFu, s, o);
                if (lane >= o) s += t;
            }
            wsum[lane] = s;
        }
        __syncthreads();
        int woff  = wid ? wsum[wid - 1] : 0;
        int total = wsum[31];
        int ex = carry + woff + inc - v;
        if (i < Nn) { rowptr[i] = ex; fill[i] = ex; }
        __syncthreads();
        if (tid == 0) carry += total;
        __syncthreads();
    }
    if (threadIdx.x == 0) rowptr[Nn] = carry;
}

__global__ void k_fill(const void* __restrict__ ei, int* __restrict__ fill,
                       int* __restrict__ colidx) {
    int e = blockIdx.x * blockDim.x + threadIdx.x;
    if (e < Ee) {
        int r = edge_at(ei, 0, e);
        int c = edge_at(ei, 1, e);
        int p = atomicAdd(&fill[r], 1);
        colidx[p] = c;
    }
}

// ---------------- aggregation (CSR gather-sum) ----------------
template <int C, bool GCN>
__global__ void k_agg(const float* __restrict__ h, float* __restrict__ out,
                      const int* __restrict__ rowptr, const int* __restrict__ colidx,
                      const float* __restrict__ dinv, const float* __restrict__ cinv) {
    constexpr int TPN = C / 4;
    constexpr int NPB = 256 / TPN;
    int node = blockIdx.x * NPB + threadIdx.x / TPN;
    if (node >= Nn) return;
    int lane = threadIdx.x % TPN;
    int s = rowptr[node], e = rowptr[node + 1];
    const float4* h4 = (const float4*)h;
    float4 acc = make_float4(0.f, 0.f, 0.f, 0.f);
    for (int p = s; p < e; p++) {
        int j = colidx[p];
        float w = GCN ? dinv[j] : 1.0f;
        float4 v = __ldg(&h4[(size_t)j * TPN + lane]);
        acc.x += v.x * w; acc.y += v.y * w; acc.z += v.z * w; acc.w += v.w * w;
    }
    float sc = GCN ? dinv[node] : cinv[node];
    acc.x *= sc; acc.y *= sc; acc.z *= sc; acc.w *= sc;
    ((float4*)out)[(size_t)node * TPN + lane] = acc;
}

// ---------------- fused dual GEMM via packed f32x2 FFMA ----------------
// out = epi(A0@B0 [+ A1@B1] + bias); epi: relu or rezero-residual
#define BM 64
#define BN 128
#define BK 16
__global__ void __launch_bounds__(256)
k_gemm(const float* __restrict__ A0, const float* __restrict__ B0,
       const float* __restrict__ A1, const float* __restrict__ B1,
       const float* __restrict__ bias,
       const float* __restrict__ res, const float* __restrict__ alphaPtr, int alphaIdx,
       float* __restrict__ out, int n, int K, int Cout, int doRelu) {
    __shared__ __align__(16) float sA[BK][BM + 2];
    __shared__ __align__(16) float sB[BK][BN];
    int bm = blockIdx.y * BM;
    int bn = blockIdx.x * BN;
    int tx = threadIdx.x % 16;   // n-group: cols tx*4..+3 and 64+tx*4..+3
    int ty = threadIdx.x / 16;   // m-group: rows ty*4..+3

    ull acc[4][4];
    #pragma unroll
    for (int i = 0; i < 4; i++)
        #pragma unroll
        for (int j = 0; j < 4; j++) acc[i][j] = 0ull;

    #pragma unroll 1
    for (int pass = 0; pass < 2; pass++) {
        const float* A = pass ? A1 : A0;
        const float* B = pass ? B1 : B0;
        if (!A) continue;
        #pragma unroll 1
        for (int k0 = 0; k0 < K; k0 += BK) {
            // A tile: one float4 per thread (64 rows x 16 k)
            {
                int row = threadIdx.x / 4;
                int k4  = (threadIdx.x % 4) * 4;
                int gr = bm + row;
                float4 v = make_float4(0.f, 0.f, 0.f, 0.f);
                if (gr < n) v = *(const float4*)&A[(size_t)gr * K + k0 + k4];
                sA[k4 + 0][row] = v.x;
                sA[k4 + 1][row] = v.y;
                sA[k4 + 2][row] = v.z;
                sA[k4 + 3][row] = v.w;
            }
            // B tile: two float4 per thread (16 k x 128 n)
            {
                int kk = threadIdx.x / 32;        // 0..7
                int n4 = (threadIdx.x % 32) * 4;  // 0..124
                int gc = bn + n4;                 // Cout % 4 == 0 always
                float4 z = make_float4(0.f, 0.f, 0.f, 0.f);
                float4 v0 = (gc < Cout) ? *(const float4*)&B[(size_t)(k0 + kk) * Cout + gc] : z;
                float4 v1 = (gc < Cout) ? *(const float4*)&B[(size_t)(k0 + kk + 8) * Cout + gc] : z;
                *(float4*)&sB[kk][n4]     = v0;
                *(float4*)&sB[kk + 8][n4] = v1;
            }
            __syncthreads();
            #pragma unroll
            for (int kk = 0; kk < BK; kk++) {
                ulonglong2 bL = *(const ulonglong2*)&sB[kk][tx * 4];
                ulonglong2 bH = *(const ulonglong2*)&sB[kk][64 + tx * 4];
                #pragma unroll
                for (int mi = 0; mi < 4; mi++) {
                    float a = sA[kk][ty * 4 + mi];
                    ull a2 = pack2(a, a);
                    acc[mi][0] = ffma2(a2, bL.x, acc[mi][0]);
                    acc[mi][1] = ffma2(a2, bL.y, acc[mi][1]);
                    acc[mi][2] = ffma2(a2, bH.x, acc[mi][2]);
                    acc[mi][3] = ffma2(a2, bH.y, acc[mi][3]);
                }
            }
            __syncthreads();
        }
    }

    float alpha = alphaPtr ? __ldg(&alphaPtr[alphaIdx]) : 0.f;
    #pragma unroll
    for (int mi = 0; mi < 4; mi++) {
        int gr = bm + ty * 4 + mi;
        if (gr >= n) continue;
        #pragma unroll
        for (int ni = 0; ni < 4; ni++) {
            int c0 = bn + ((ni < 2) ? (tx * 4 + ni * 2) : (64 + tx * 4 + (ni - 2) * 2));
            float fx, fy;
            unpack2(acc[mi][ni], fx, fy);
            float vv[2] = {fx, fy};
            #pragma unroll
            for (int u = 0; u < 2; u++) {
                int gc = c0 + u;
                if (gc >= Cout) continue;
                float val = vv[u] + __ldg(&bias[gc]);
                if (doRelu) val = fmaxf(val, 0.f);
                if (res) val = res[(size_t)gr * Cout + gc] + alpha * val;
                out[(size_t)gr * Cout + gc] = val;
            }
        }
    }
}

// ---------------- launch ----------------
extern "C" void kernel_launch(void* const* d_in, const int* in_sizes, int n_in,
                              void* d_out, int out_size) {
    const float* x     = (const float*)d_in[0];
    const void*  ei    = d_in[1];
    const float* alpha = (const float*)d_in[2];
    const float* W0 = (const float*)d_in[3];  const float* b0 = (const float*)d_in[4];
    const float* W1 = (const float*)d_in[5];  const float* R1 = (const float*)d_in[6];  const float* b1 = (const float*)d_in[7];
    const float* W2 = (const float*)d_in[8];  const float* R2 = (const float*)d_in[9];  const float* b2 = (const float*)d_in[10];
    const float* W3 = (const float*)d_in[11]; const float* b3 = (const float*)d_in[12];
    const float* W4 = (const float*)d_in[13]; const float* R4 = (const float*)d_in[14]; const float* b4 = (const float*)d_in[15];
    float* out = (float*)d_out;

    float *hA, *hB, *agg, *dinv, *cinv;
    int *degi, *rowptr, *fill, *colidx;
    cudaGetSymbolAddress((void**)&degi,   g_degi);
    cudaGetSymbolAddress((void**)&dinv,   g_dinv);
    cudaGetSymbolAddress((void**)&cinv,   g_cinv);
    cudaGetSymbolAddress((void**)&rowptr, g_rowptr);
    cudaGetSymbolAddress((void**)&fill,   g_fill);
    cudaGetSymbolAddress((void**)&colidx, g_colidx);
    cudaGetSymbolAddress((void**)&hA,     g_hA);
    cudaGetSymbolAddress((void**)&hB,     g_hB);
    cudaGetSymbolAddress((void**)&agg,    g_agg);

    const int NB_N = (Nn + 255) / 256;
    const int NB_E = (Ee + 255) / 256;
    const int MT   = (Nn + BM - 1) / BM;   // 1563

    k_detect<<<1, 32>>>((const int*)ei);
    k_zero<<<NB_N, 256>>>(degi, Nn);
    k_count<<<NB_E, 256>>>(ei, degi);
    k_stats<<<NB_N, 256>>>(degi, dinv, cinv);
    k_scan<<<1, 1024>>>(degi, rowptr, fill);
    k_fill<<<NB_E, 256>>>(ei, fill, colidx);

    // layer 0: GCN, C=128, rezero residual (alpha[0])
    k_agg<128, true><<<Nn / 8, 256>>>(x, agg, rowptr, colidx, dinv, cinv);
    k_gemm<<<dim3(1, MT), 256>>>(agg, W0, nullptr, nullptr, b0, x, alpha, 0, hA, Nn, 128, 128, 0);

    // layer 1: SAGE 128->256 + relu
    k_agg<128, false><<<Nn / 8, 256>>>(hA, agg, rowptr, colidx, dinv, cinv);
    k_gemm<<<dim3(2, MT), 256>>>(agg, W1, hA, R1, b1, nullptr, nullptr, 0, hB, Nn, 128, 256, 1);

    // layer 2: SAGE 256->256 + relu
    k_agg<256, false><<<Nn / 4, 256>>>(hB, agg, rowptr, colidx, dinv, cinv);
    k_gemm<<<dim3(2, MT), 256>>>(agg, W2, hB, R2, b2, nullptr, nullptr, 0, hA, Nn, 256, 256, 1);

    // layer 3: GCN, C=256, rezero residual (alpha[3])
    k_agg<256, true><<<Nn / 4, 256>>>(hA, agg, rowptr, colidx, dinv, cinv);
    k_gemm<<<dim3(2, MT), 256>>>(agg, W3, nullptr, nullptr, b3, hA, alpha, 3, hB, Nn, 256, 256, 0);

    // layer 4: SAGE 256->112, no relu
    k_agg<256, false><<<Nn / 4, 256>>>(hB, agg, rowptr, colidx, dinv, cinv);
    k_gemm<<<dim3(1, MT), 256>>>(agg, W4, hB, R4, b4, nullptr, nullptr, 0, out, Nn, 256, 112, 0);
}